// round 1
// baseline (speedup 1.0000x reference)
#include <cuda_runtime.h>

// out = noised + 0.1f * noise   (elementwise, N = 50,331,648 fp32)
// Pure HBM-streaming kernel: 128-bit vectorized, flat launch.

__global__ void __launch_bounds__(256) gaussian_noise_axpy4(
    const float4* __restrict__ noised,
    const float4* __restrict__ noise,
    float4* __restrict__ out,
    int n4)
{
    int i = blockIdx.x * blockDim.x + threadIdx.x;
    if (i < n4) {
        float4 a = noised[i];
        float4 b = noise[i];
        float4 r;
        r.x = fmaf(0.1f, b.x, a.x);
        r.y = fmaf(0.1f, b.y, a.y);
        r.z = fmaf(0.1f, b.z, a.z);
        r.w = fmaf(0.1f, b.w, a.w);
        out[i] = r;
    }
}

// Scalar tail fallback (not expected to trigger for this shape, but keeps the
// kernel correct for any element count).
__global__ void gaussian_noise_axpy_tail(
    const float* __restrict__ noised,
    const float* __restrict__ noise,
    float* __restrict__ out,
    int start, int n)
{
    int i = start + blockIdx.x * blockDim.x + threadIdx.x;
    if (i < n) {
        out[i] = fmaf(0.1f, noise[i], noised[i]);
    }
}

extern "C" void kernel_launch(void* const* d_in, const int* in_sizes, int n_in,
                              void* d_out, int out_size)
{
    const float* noised = (const float*)d_in[0];
    const float* noise  = (const float*)d_in[1];
    float* out = (float*)d_out;
    int n = in_sizes[0];

    int n4 = n >> 2;               // float4 count
    if (n4 > 0) {
        int threads = 256;
        int blocks = (n4 + threads - 1) / threads;
        gaussian_noise_axpy4<<<blocks, threads>>>(
            (const float4*)noised, (const float4*)noise, (float4*)out, n4);
    }
    int done = n4 << 2;
    if (done < n) {
        int rem = n - done;
        gaussian_noise_axpy_tail<<<(rem + 255) / 256, 256>>>(noised, noise, out, done, n);
    }
}